// round 1
// baseline (speedup 1.0000x reference)
#include <cuda_runtime.h>
#include <math.h>

#define BB 4
#define HH 48
#define WW 48
#define LL (HH*WW)      /* 2304 */
#define DM 96
#define DI 192
#define NS 16
#define RR 6
#define KK 3
#define XD 40           /* padded x_dbl row: [r0..r5, pad, pad, B0,C0,B1,C1,...,B15,C15] */

/* ---------------- scratch (device globals: allocation-free) ---------------- */
__device__ float  g_xcraw[BB*LL*DI];            /* conv input  (b, l, d)   */
__device__ float  g_z    [BB*LL*DI];            /* silu(z)     (b, l, d)   */
__device__ float  g_xch  [BB*LL*DI];            /* conv output (b, l, d)   */
__device__ float  g_xdbl [BB*KK*LL*XD];         /* x_dbl, scan-position-major rows */
__device__ float2 g_pre  [(size_t)BB*KK*DI*LL]; /* {e1, dt*u}, chain-major */
__device__ float  g_ys   [KK][BB*LL*DI];        /* per-direction scan outputs at logical pos */

__device__ __forceinline__ float fsilu(float v){ return v / (1.f + __expf(-v)); }

/* ------------- in_proj: xz = x @ W^T ; split; silu(z) ------------- */
__global__ void k_inproj(const float* __restrict__ x, const float* __restrict__ w)
{
    __shared__ float xt[16*DM];
    int tb = blockIdx.x * 16;                    /* combined token index base (b*LL + l) */
    for (int i = threadIdx.x; i < 16*DM; i += blockDim.x)
        xt[i] = x[(size_t)tb*DM + i];
    __syncthreads();
    int j = threadIdx.x;                          /* 0..383 output feature */
    float acc[16];
#pragma unroll
    for (int t=0;t<16;t++) acc[t]=0.f;
    const float4* w4 = reinterpret_cast<const float4*>(w + j*DM);
#pragma unroll
    for (int c4 = 0; c4 < DM/4; c4++){
        float4 wv = w4[c4];
#pragma unroll
        for (int t=0;t<16;t++){
            float4 xv = *reinterpret_cast<const float4*>(&xt[t*DM + c4*4]);
            acc[t] += wv.x*xv.x + wv.y*xv.y + wv.z*xv.z + wv.w*xv.w;
        }
    }
    if (j < DI){
#pragma unroll
        for (int t=0;t<16;t++) g_xcraw[(size_t)(tb+t)*DI + j] = acc[t];
    } else {
        int jz = j - DI;
#pragma unroll
        for (int t=0;t<16;t++) g_z[(size_t)(tb+t)*DI + jz] = fsilu(acc[t]);
    }
}

/* ------------- depthwise 3x3 conv (SAME) + bias + silu ------------- */
__global__ void k_conv(const float* __restrict__ cw, const float* __restrict__ cb)
{
    int l = blockIdx.x;
    int b = blockIdx.y;
    int d = threadIdx.x;
    int h = l / WW, w = l % WW;
    float s = cb[d];
    const float* base = g_xcraw + (size_t)b*LL*DI + d;
#pragma unroll
    for (int kh=0; kh<3; kh++){
        int h2 = h + kh - 1;
        if ((unsigned)h2 >= HH) continue;
#pragma unroll
        for (int kw=0; kw<3; kw++){
            int w2 = w + kw - 1;
            if ((unsigned)w2 >= WW) continue;
            s += base[(size_t)(h2*WW + w2)*DI] * cw[d*9 + kh*3 + kw];
        }
    }
    g_xch[((size_t)b*LL + l)*DI + d] = fsilu(s);
}

/* ------------- x_proj: x_dbl[b,k,p,c] = sum_d W[k,c,d]*xc[b,spat,d] ------------- */
__global__ void k_xproj(const float* __restrict__ xw)
{
    __shared__ float tok[32*DI];                  /* 24 KB, reused as staging */
    int tb = blockIdx.x * 32;
    int b  = tb / LL;
    int l0 = tb % LL;
    for (int i = threadIdx.x; i < 32*DI; i += blockDim.x)
        tok[i] = g_xch[((size_t)b*LL + l0)*DI + i];
    __syncthreads();
    float acc[32];
    int kc = threadIdx.x;
    int k = kc / 38, c = kc % 38;
    bool active = kc < KK*38;
    if (active){
#pragma unroll
        for (int t=0;t<32;t++) acc[t]=0.f;
        const float4* w4 = reinterpret_cast<const float4*>(xw + (size_t)(k*38 + c)*DI);
        for (int d4 = 0; d4 < DI/4; d4++){
            float4 wv = w4[d4];
#pragma unroll
            for (int t=0;t<32;t++){
                float4 xv = *reinterpret_cast<const float4*>(&tok[t*DI + d4*4]);
                acc[t] += wv.x*xv.x + wv.y*xv.y + wv.z*xv.z + wv.w*xv.w;
            }
        }
    }
    __syncthreads();                              /* finished reading tok */
    float* stage = tok;                           /* 96 rows x 40 floats = 3840 <= 6144 */
    if (active){
        int slot = (c < RR) ? c : (c < RR+NS ? 8 + 2*(c-RR) : 9 + 2*(c-RR-NS));
#pragma unroll
        for (int t=0;t<32;t++) stage[(k*32+t)*XD + slot] = acc[t];
    }
    __syncthreads();
    for (int i = threadIdx.x; i < 96*XD; i += blockDim.x){
        int rr = i / XD, slot = i % XD;
        int k2 = rr / 32, t = rr % 32;
        int lsp = l0 + t;
        /* spatial lsp -> scan position p for direction k2 */
        int p = (k2==0) ? lsp : (k2==1 ? (lsp % WW)*HH + lsp/WW : LL-1-lsp);
        g_xdbl[(((size_t)b*KK + k2)*LL + p)*XD + slot] = stage[i];
    }
}

/* ------------- precompute: dt = softplus(dtw . r + bias); e1 = exp(dt*A0); dtu = dt*u ------------- */
__global__ void k_delta(const float* __restrict__ dtw_g, const float* __restrict__ dtb_g,
                        const float* __restrict__ alog)
{
    __shared__ float  s_r[32][RR];
    __shared__ float2 stage[DI][8];
    int d  = threadIdx.x;
    int k  = blockIdx.y, b = blockIdx.z;
    int l0 = blockIdx.x * 32;
    float dtw[RR];
#pragma unroll
    for (int r=0;r<RR;r++) dtw[r] = dtw_g[(size_t)(k*DI+d)*RR + r];
    float bias = dtb_g[k*DI + d];
    float A0   = -__expf(alog[(size_t)(k*DI+d)*NS]);
    const float* xr = g_xdbl + ((size_t)(b*KK+k)*LL)*XD;
    {
        int t = threadIdx.x / RR, r = threadIdx.x % RR;   /* 192 = 32*6 exactly */
        s_r[t][r] = xr[(size_t)(l0+t)*XD + r];
    }
    __syncthreads();
    size_t bk_base = ((size_t)(b*KK+k)*DI) * LL;
    for (int sub=0; sub<4; sub++){
#pragma unroll
        for (int t=0;t<8;t++){
            int p = l0 + sub*8 + t;
            int sp;
            if (k==0)      sp = p;
            else if (k==1) sp = (p % HH)*WW + p/HH;
            else           sp = LL-1-p;
            float u = g_xch[((size_t)b*LL + sp)*DI + d];
            float s = bias;
#pragma unroll
            for (int r=0;r<RR;r++) s += dtw[r]*s_r[sub*8+t][r];
            float es = __expf(s);
            float dt = (s > 15.f) ? s : log1pf(es);
            float e1 = __expf(dt * A0);
            stage[d][t] = make_float2(e1, dt*u);
        }
        __syncthreads();
        for (int i = threadIdx.x; i < DI*8; i += DI){
            int dd = i >> 3, tt = i & 7;
            g_pre[bk_base + (size_t)dd*LL + (size_t)(l0 + sub*8 + tt)] = stage[dd][tt];
        }
        __syncthreads();
    }
}

/* ------------- selective scan: 16 lanes = 16 states, 2 chains per warp ------------- */
__global__ void k_scan(const float* __restrict__ alog)
{
    int tid   = threadIdx.x;
    int chain = blockIdx.x * 16 + (tid >> 4);
    int lane  = tid & 15;
    int b   = chain / (KK*DI);
    int rem = chain % (KK*DI);
    int k   = rem / DI;
    int d   = rem % DI;

    float An = -__expf(alog[(size_t)(k*DI+d)*NS + lane]);
    float A0 = __shfl_sync(0xffffffffu, An, 0, 16);
    float ratio = An / A0;
    float pf = rintf(ratio);
    int   pi = (int)pf;
    bool exact = (fabsf(ratio - pf) < 1e-3f) && pi >= 1 && pi <= 31 && A0 < 0.f;
    bool bt0 = pi & 1, bt1 = pi & 2, bt2 = pi & 4, bt3 = pi & 8, bt4 = pi & 16;

    const float2* pre   = g_pre + (size_t)chain * LL;
    const float*  bcrow = g_xdbl + ((size_t)(b*KK+k)*LL)*XD + 8 + 2*lane;
    float*        yout  = g_ys[k] + ((size_t)b*LL)*DI + d;

    int hh = 0, wcol = 0;
    float h = 0.f;
#pragma unroll 4
    for (int l = 0; l < LL; l++){
        float2 ed = pre[l];
        float2 bc = *reinterpret_cast<const float2*>(bcrow + (size_t)l*XD);
        float a;
        if (exact){
            float e = ed.x;
            float acc = bt0 ? e : 1.f;
            e = e*e; if (bt1) acc *= e;
            e = e*e; if (bt2) acc *= e;
            e = e*e; if (bt3) acc *= e;
            e = e*e; if (bt4) acc *= e;
            a = acc;
        } else {
            a = exp2f(__log2f(ed.x) * ratio);     /* generic fallback */
        }
        h = a*h + ed.y * bc.x;
        float ps = h * bc.y;
        ps += __shfl_xor_sync(0xffffffffu, ps, 8, 16);
        ps += __shfl_xor_sync(0xffffffffu, ps, 4, 16);
        ps += __shfl_xor_sync(0xffffffffu, ps, 2, 16);
        ps += __shfl_xor_sync(0xffffffffu, ps, 1, 16);
        int pos;
        if (k == 0)      pos = l;
        else if (k == 1) pos = hh*WW + wcol;
        else             pos = LL-1-l;
        if (lane == 0) yout[(size_t)pos*DI] = ps;
        if (k == 1){ hh++; if (hh == HH){ hh = 0; wcol++; } }
    }
}

/* ------------- merge + D-term + gating + out_proj ------------- */
__global__ void k_out(const float* __restrict__ ow, const float* __restrict__ Ds,
                      float* __restrict__ out)
{
    __shared__ float yz[32*DI];
    int tb = blockIdx.x * 32;
    size_t base = (size_t)tb * DI;
    for (int i = threadIdx.x; i < 32*DI; i += blockDim.x){
        int dd = i % DI;
        float dsum = Ds[dd] + Ds[DI+dd] + Ds[2*DI+dd];
        float v = g_ys[0][base+i] + g_ys[1][base+i] + g_ys[2][base+i]
                + dsum * g_xch[base+i];
        yz[i] = v * g_z[base+i];
    }
    __syncthreads();
    int j = threadIdx.x;
    if (j < DM){
        float acc[32];
#pragma unroll
        for (int t=0;t<32;t++) acc[t]=0.f;
        const float4* w4 = reinterpret_cast<const float4*>(ow + (size_t)j*DI);
        for (int d4=0; d4<DI/4; d4++){
            float4 wv = w4[d4];
#pragma unroll
            for (int t=0;t<32;t++){
                float4 xv = *reinterpret_cast<const float4*>(&yz[t*DI + d4*4]);
                acc[t] += wv.x*xv.x + wv.y*xv.y + wv.z*xv.z + wv.w*xv.w;
            }
        }
#pragma unroll
        for (int t=0;t<32;t++) out[(size_t)(tb+t)*DM + j] = acc[t];
    }
}

/* ---------------- launcher ---------------- */
extern "C" void kernel_launch(void* const* d_in, const int* in_sizes, int n_in,
                              void* d_out, int out_size)
{
    const float* x    = (const float*)d_in[0];
    /* d_in[1] = illum, unused by the reference */
    const float* inw  = (const float*)d_in[2];
    const float* cw   = (const float*)d_in[3];
    const float* cb   = (const float*)d_in[4];
    const float* xw   = (const float*)d_in[5];
    const float* dtw  = (const float*)d_in[6];
    const float* dtb  = (const float*)d_in[7];
    const float* alog = (const float*)d_in[8];
    const float* Ds   = (const float*)d_in[9];
    const float* ow   = (const float*)d_in[10];
    float* out = (float*)d_out;

    k_inproj<<<BB*LL/16, 384>>>(x, inw);
    k_conv  <<<dim3(LL, BB), DI>>>(cw, cb);
    k_xproj <<<BB*LL/32, 128>>>(xw);
    k_delta <<<dim3(LL/32, KK, BB), DI>>>(dtw, dtb, alog);
    k_scan  <<<BB*KK*DI/16, 256>>>(alog);
    k_out   <<<BB*LL/32, 128>>>(ow, Ds, out);
}

// round 2
// speedup vs baseline: 4.8350x; 4.8350x over previous
#include <cuda_runtime.h>
#include <math.h>

#define BB 4
#define HH 48
#define WW 48
#define LL (HH*WW)      /* 2304 */
#define DM 96
#define DI 192
#define NS 16
#define RR 6
#define KK 3
#define XD 40           /* padded x_dbl row: [r0..r5, pad, pad, B0,C0,...,B15,C15] */
#define CH (BB*KK*DI)   /* 2304 chains */
#define SS 32           /* scan segments */
#define LSEG (LL/SS)    /* 72 */

/* ---------------- scratch (device globals: allocation-free) ---------------- */
__device__ float  g_xcraw[BB*LL*DI];
__device__ float  g_z    [BB*LL*DI];
__device__ float  g_xch  [BB*LL*DI];
__device__ float  g_xdbl [BB*KK*LL*XD];
__device__ float2 g_pre  [(size_t)BB*KK*LL*DI];   /* {e1, dt*u}  layout [bk][l][d] */
__device__ float  g_segq [SS][NS][CH];
__device__ float  g_segp [SS][CH];
__device__ float  g_hin  [SS][NS][CH];
__device__ float  g_ys   [KK][BB*LL*DI];

__device__ __forceinline__ float fsilu(float v){ return v / (1.f + __expf(-v)); }

/* ------------- in_proj: xz = x @ W^T ; split; silu(z) ------------- */
__global__ void k_inproj(const float* __restrict__ x, const float* __restrict__ w)
{
    __shared__ float xt[16*DM];
    int tb = blockIdx.x * 16;
    for (int i = threadIdx.x; i < 16*DM; i += blockDim.x)
        xt[i] = x[(size_t)tb*DM + i];
    __syncthreads();
    int j = threadIdx.x;
    float acc[16];
#pragma unroll
    for (int t=0;t<16;t++) acc[t]=0.f;
    const float4* w4 = reinterpret_cast<const float4*>(w + j*DM);
#pragma unroll
    for (int c4 = 0; c4 < DM/4; c4++){
        float4 wv = w4[c4];
#pragma unroll
        for (int t=0;t<16;t++){
            float4 xv = *reinterpret_cast<const float4*>(&xt[t*DM + c4*4]);
            acc[t] += wv.x*xv.x + wv.y*xv.y + wv.z*xv.z + wv.w*xv.w;
        }
    }
    if (j < DI){
#pragma unroll
        for (int t=0;t<16;t++) g_xcraw[(size_t)(tb+t)*DI + j] = acc[t];
    } else {
        int jz = j - DI;
#pragma unroll
        for (int t=0;t<16;t++) g_z[(size_t)(tb+t)*DI + jz] = fsilu(acc[t]);
    }
}

/* ------------- depthwise 3x3 conv (SAME) + bias + silu ------------- */
__global__ void k_conv(const float* __restrict__ cw, const float* __restrict__ cb)
{
    int l = blockIdx.x;
    int b = blockIdx.y;
    int d = threadIdx.x;
    int h = l / WW, w = l % WW;
    float s = cb[d];
    const float* base = g_xcraw + (size_t)b*LL*DI + d;
#pragma unroll
    for (int kh=0; kh<3; kh++){
        int h2 = h + kh - 1;
        if ((unsigned)h2 >= HH) continue;
#pragma unroll
        for (int kw=0; kw<3; kw++){
            int w2 = w + kw - 1;
            if ((unsigned)w2 >= WW) continue;
            s += base[(size_t)(h2*WW + w2)*DI] * cw[d*9 + kh*3 + kw];
        }
    }
    g_xch[((size_t)b*LL + l)*DI + d] = fsilu(s);
}

/* ------------- x_proj into permuted, padded rows ------------- */
__global__ void k_xproj(const float* __restrict__ xw)
{
    __shared__ float tok[32*DI];
    int tb = blockIdx.x * 32;
    int b  = tb / LL;
    int l0 = tb % LL;
    for (int i = threadIdx.x; i < 32*DI; i += blockDim.x)
        tok[i] = g_xch[((size_t)b*LL + l0)*DI + i];
    __syncthreads();
    float acc[32];
    int kc = threadIdx.x;
    int k = kc / 38, c = kc % 38;
    bool active = kc < KK*38;
    if (active){
#pragma unroll
        for (int t=0;t<32;t++) acc[t]=0.f;
        const float4* w4 = reinterpret_cast<const float4*>(xw + (size_t)(k*38 + c)*DI);
        for (int d4 = 0; d4 < DI/4; d4++){
            float4 wv = w4[d4];
#pragma unroll
            for (int t=0;t<32;t++){
                float4 xv = *reinterpret_cast<const float4*>(&tok[t*DI + d4*4]);
                acc[t] += wv.x*xv.x + wv.y*xv.y + wv.z*xv.z + wv.w*xv.w;
            }
        }
    }
    __syncthreads();
    float* stage = tok;
    if (active){
        int slot = (c < RR) ? c : (c < RR+NS ? 8 + 2*(c-RR) : 9 + 2*(c-RR-NS));
#pragma unroll
        for (int t=0;t<32;t++) stage[(k*32+t)*XD + slot] = acc[t];
    }
    __syncthreads();
    for (int i = threadIdx.x; i < 96*XD; i += blockDim.x){
        int rr = i / XD, slot = i % XD;
        int k2 = rr / 32, t = rr % 32;
        int lsp = l0 + t;
        int p = (k2==0) ? lsp : (k2==1 ? (lsp % WW)*HH + lsp/WW : LL-1-lsp);
        g_xdbl[(((size_t)b*KK + k2)*LL + p)*XD + slot] = stage[i];
    }
}

/* ------------- precompute {e1, dt*u} into [bk][l][d] ------------- */
__global__ void k_delta(const float* __restrict__ dtw_g, const float* __restrict__ dtb_g,
                        const float* __restrict__ alog)
{
    __shared__ float s_r[32][RR];
    int d  = threadIdx.x;
    int k  = blockIdx.y, b = blockIdx.z;
    int l0 = blockIdx.x * 32;
    float dtw[RR];
#pragma unroll
    for (int r=0;r<RR;r++) dtw[r] = dtw_g[(size_t)(k*DI+d)*RR + r];
    float bias = dtb_g[k*DI + d];
    float A0   = -__expf(alog[(size_t)(k*DI+d)*NS]);
    const float* xr = g_xdbl + ((size_t)(b*KK+k)*LL)*XD;
    {
        int t = threadIdx.x / RR, r = threadIdx.x % RR;   /* 192 = 32*6 */
        s_r[t][r] = xr[(size_t)(l0+t)*XD + r];
    }
    __syncthreads();
    float2* po = g_pre + ((size_t)(b*KK+k)*LL + l0)*DI + d;
#pragma unroll 4
    for (int t=0;t<32;t++){
        int p = l0 + t;
        int sp;
        if (k==0)      sp = p;
        else if (k==1) sp = (p % HH)*WW + p/HH;
        else           sp = LL-1-p;
        float u = g_xch[((size_t)b*LL + sp)*DI + d];
        float s = bias;
#pragma unroll
        for (int r=0;r<RR;r++) s += dtw[r]*s_r[t][r];
        float es = __expf(s);
        float dt = (s > 15.f) ? s : log1pf(es);
        float e1 = __expf(dt * A0);
        po[(size_t)t*DI] = make_float2(e1, dt*u);
    }
}

/* ------------- scan pass 1: per-segment (prod e1, q) with h0 = 0 ------------- */
__global__ void k_scan1(const float* __restrict__ alog)
{
    int t = blockIdx.x*blockDim.x + threadIdx.x;
    int seg = t / CH, chain = t % CH;
    int bk = chain / DI, d = chain % DI, k = bk % KK;
    int lane = d & 31;

    const float* ar = alog + (size_t)(k*DI+d)*NS;
    float a0 = ar[0];
    bool unit = true;
#pragma unroll
    for (int n=0;n<NS;n++){
        float r = __expf(ar[n]-a0);
        unit = unit && (fabsf(r-(float)(n+1)) < 1e-3f);
    }
    bool wunit = __all_sync(0xffffffffu, unit);

    const float2* pre = g_pre + (size_t)bk*LL*DI + d;
    const float*  bcr = g_xdbl + (size_t)bk*LL*XD + 8 + lane;
    int l0 = seg * LSEG;

    float h[NS];
#pragma unroll
    for (int n=0;n<NS;n++) h[n]=0.f;
    float pe = 1.f;

    if (wunit){
#pragma unroll 2
        for (int i=0;i<LSEG;i++){
            int l = l0 + i;
            float2 ed = pre[(size_t)l*DI];
            float bcv = bcr[(size_t)l*XD];
            float du = ed.y;
            pe *= ed.x;
            float a = ed.x;
#pragma unroll
            for (int n=0;n<NS;n++){
                float bn = __shfl_sync(0xffffffffu, bcv, 2*n, 32);
                h[n] = a*h[n] + du*bn;
                a *= ed.x;
            }
        }
    } else {
        float rn[NS];
#pragma unroll
        for (int n=0;n<NS;n++) rn[n] = __expf(ar[n]-a0);
        for (int i=0;i<LSEG;i++){
            int l = l0 + i;
            float2 ed = pre[(size_t)l*DI];
            float bcv = bcr[(size_t)l*XD];
            float du = ed.y;
            pe *= ed.x;
            float lg = __log2f(ed.x);
#pragma unroll
            for (int n=0;n<NS;n++){
                float bn = __shfl_sync(0xffffffffu, bcv, 2*n, 32);
                h[n] = exp2f(lg*rn[n])*h[n] + du*bn;
            }
        }
    }
#pragma unroll
    for (int n=0;n<NS;n++) g_segq[seg][n][chain] = h[n];
    g_segp[seg][chain] = pe;
}

/* ------------- combine: sequential over segments per (chain, n) ------------- */
__global__ void k_comb(const float* __restrict__ alog)
{
    int t = blockIdx.x*blockDim.x + threadIdx.x;   /* CH*NS threads */
    int n = t / CH, chain = t % CH;
    int d = chain % DI, k = (chain / DI) % KK;
    const float* ar = alog + (size_t)(k*DI+d)*NS;
    float ratio = __expf(ar[n] - ar[0]);
    float h = 0.f;
    g_hin[0][n][chain] = 0.f;
#pragma unroll 4
    for (int s=1;s<SS;s++){
        float pe = g_segp[s-1][chain];
        float q  = g_segq[s-1][n][chain];
        h = exp2f(__log2f(pe)*ratio)*h + q;
        g_hin[s][n][chain] = h;
    }
}

/* ------------- scan pass 2: rescan with correct h_init, emit y ------------- */
__global__ void k_scan2(const float* __restrict__ alog)
{
    int t = blockIdx.x*blockDim.x + threadIdx.x;
    int seg = t / CH, chain = t % CH;
    int bk = chain / DI, d = chain % DI, k = bk % KK;
    int b = bk / KK;
    int lane = d & 31;

    const float* ar = alog + (size_t)(k*DI+d)*NS;
    float a0 = ar[0];
    bool unit = true;
#pragma unroll
    for (int n=0;n<NS;n++){
        float r = __expf(ar[n]-a0);
        unit = unit && (fabsf(r-(float)(n+1)) < 1e-3f);
    }
    bool wunit = __all_sync(0xffffffffu, unit);

    const float2* pre = g_pre + (size_t)bk*LL*DI + d;
    const float*  bcr = g_xdbl + (size_t)bk*LL*XD + 8 + lane;
    float* yout = g_ys[k] + (size_t)b*LL*DI + d;
    int l0 = seg * LSEG;

    float h[NS];
#pragma unroll
    for (int n=0;n<NS;n++) h[n] = g_hin[seg][n][chain];

    int hh = l0 % HH, wc = l0 / HH;   /* for k==1 position tracking */

    if (wunit){
#pragma unroll 2
        for (int i=0;i<LSEG;i++){
            int l = l0 + i;
            float2 ed = pre[(size_t)l*DI];
            float bcv = bcr[(size_t)l*XD];
            float du = ed.y;
            float a = ed.x;
            float y = 0.f;
#pragma unroll
            for (int n=0;n<NS;n++){
                float bn = __shfl_sync(0xffffffffu, bcv, 2*n, 32);
                float cn = __shfl_sync(0xffffffffu, bcv, 2*n+1, 32);
                h[n] = a*h[n] + du*bn;
                y += h[n]*cn;
                a *= ed.x;
            }
            int pos;
            if (k == 0)      pos = l;
            else if (k == 1) pos = hh*WW + wc;
            else             pos = LL-1-l;
            yout[(size_t)pos*DI] = y;
            if (k == 1){ hh++; if (hh == HH){ hh = 0; wc++; } }
        }
    } else {
        float rn[NS];
#pragma unroll
        for (int n=0;n<NS;n++) rn[n] = __expf(ar[n]-a0);
        for (int i=0;i<LSEG;i++){
            int l = l0 + i;
            float2 ed = pre[(size_t)l*DI];
            float bcv = bcr[(size_t)l*XD];
            float du = ed.y;
            float lg = __log2f(ed.x);
            float y = 0.f;
#pragma unroll
            for (int n=0;n<NS;n++){
                float bn = __shfl_sync(0xffffffffu, bcv, 2*n, 32);
                float cn = __shfl_sync(0xffffffffu, bcv, 2*n+1, 32);
                h[n] = exp2f(lg*rn[n])*h[n] + du*bn;
                y += h[n]*cn;
            }
            int pos;
            if (k == 0)      pos = l;
            else if (k == 1) pos = hh*WW + wc;
            else             pos = LL-1-l;
            yout[(size_t)pos*DI] = y;
            if (k == 1){ hh++; if (hh == HH){ hh = 0; wc++; } }
        }
    }
}

/* ------------- merge + D-term + gating + out_proj ------------- */
__global__ void k_out(const float* __restrict__ ow, const float* __restrict__ Ds,
                      float* __restrict__ out)
{
    __shared__ float yz[32*DI];
    int tb = blockIdx.x * 32;
    size_t base = (size_t)tb * DI;
    for (int i = threadIdx.x; i < 32*DI; i += blockDim.x){
        int dd = i % DI;
        float dsum = Ds[dd] + Ds[DI+dd] + Ds[2*DI+dd];
        float v = g_ys[0][base+i] + g_ys[1][base+i] + g_ys[2][base+i]
                + dsum * g_xch[base+i];
        yz[i] = v * g_z[base+i];
    }
    __syncthreads();
    int j = threadIdx.x;
    if (j < DM){
        float acc[32];
#pragma unroll
        for (int t=0;t<32;t++) acc[t]=0.f;
        const float4* w4 = reinterpret_cast<const float4*>(ow + (size_t)j*DI);
        for (int d4=0; d4<DI/4; d4++){
            float4 wv = w4[d4];
#pragma unroll
            for (int t=0;t<32;t++){
                float4 xv = *reinterpret_cast<const float4*>(&yz[t*DI + d4*4]);
                acc[t] += wv.x*xv.x + wv.y*xv.y + wv.z*xv.z + wv.w*xv.w;
            }
        }
#pragma unroll
        for (int t=0;t<32;t++) out[(size_t)(tb+t)*DM + j] = acc[t];
    }
}

/* ---------------- launcher ---------------- */
extern "C" void kernel_launch(void* const* d_in, const int* in_sizes, int n_in,
                              void* d_out, int out_size)
{
    const float* x    = (const float*)d_in[0];
    const float* inw  = (const float*)d_in[2];
    const float* cw   = (const float*)d_in[3];
    const float* cb   = (const float*)d_in[4];
    const float* xw   = (const float*)d_in[5];
    const float* dtw  = (const float*)d_in[6];
    const float* dtb  = (const float*)d_in[7];
    const float* alog = (const float*)d_in[8];
    const float* Ds   = (const float*)d_in[9];
    const float* ow   = (const float*)d_in[10];
    float* out = (float*)d_out;

    k_inproj<<<BB*LL/16, 384>>>(x, inw);
    k_conv  <<<dim3(LL, BB), DI>>>(cw, cb);
    k_xproj <<<BB*LL/32, 128>>>(xw);
    k_delta <<<dim3(LL/32, KK, BB), DI>>>(dtw, dtb, alog);
    k_scan1 <<<SS*CH/256, 256>>>(alog);
    k_comb  <<<CH*NS/256, 256>>>(alog);
    k_scan2 <<<SS*CH/256, 256>>>(alog);
    k_out   <<<BB*LL/32, 128>>>(ow, Ds, out);
}

// round 3
// speedup vs baseline: 5.0332x; 1.0410x over previous
#include <cuda_runtime.h>
#include <math.h>

#define BB 4
#define HH 48
#define WW 48
#define LL (HH*WW)      /* 2304 */
#define DM 96
#define DI 192
#define NS 16
#define RR 6
#define KK 3
#define XD 40           /* row: [r0..r5, pad, pad, B0..B15, C0..C15] */
#define CH (BB*KK*DI)   /* 2304 chains */
#define SS 64           /* scan segments */
#define LSEG (LL/SS)    /* 36 */

typedef unsigned long long u64;
union F2U { float2 f; u64 u; };
union F4U { float4 f; u64 u[2]; };

__device__ __forceinline__ u64 F2P(float x, float y){ F2U t; t.f=make_float2(x,y); return t.u; }
__device__ __forceinline__ float LOF(u64 v){ F2U t; t.u=v; return t.f.x; }
__device__ __forceinline__ float HIF(u64 v){ F2U t; t.u=v; return t.f.y; }
__device__ __forceinline__ u64 fma2(u64 a,u64 b,u64 c){ u64 d; asm("fma.rn.f32x2 %0,%1,%2,%3;":"=l"(d):"l"(a),"l"(b),"l"(c)); return d; }
__device__ __forceinline__ u64 mul2(u64 a,u64 b){ u64 d; asm("mul.rn.f32x2 %0,%1,%2;":"=l"(d):"l"(a),"l"(b)); return d; }

/* ---------------- scratch ---------------- */
__device__ float  g_xcraw[BB*LL*DI];
__device__ float  g_z    [BB*LL*DI];
__device__ float  g_xch  [BB*LL*DI];
__device__ float  g_xdbl [BB*KK*LL*XD];
__device__ float2 g_pre  [(size_t)BB*KK*LL*DI];   /* {e1, dt*u}  [bk][l][d] */
__device__ float  g_segq [SS][NS][CH];
__device__ float  g_segp [SS][CH];
__device__ float  g_hin  [SS][NS][CH];
__device__ float  g_ys   [KK][BB*LL*DI];

__device__ __forceinline__ float fsilu(float v){ return v / (1.f + __expf(-v)); }

/* ------------- in_proj ------------- */
__global__ void k_inproj(const float* __restrict__ x, const float* __restrict__ w)
{
    __shared__ float xt[16*DM];
    int tb = blockIdx.x * 16;
    for (int i=threadIdx.x;i<16*DM;i+=blockDim.x) xt[i]=x[(size_t)tb*DM+i];
    __syncthreads();
    int j = threadIdx.x;
    u64 acc[16];
#pragma unroll
    for(int t=0;t<16;t++) acc[t]=0ull;
    const float4* w4 = reinterpret_cast<const float4*>(w + j*DM);
#pragma unroll
    for(int c4=0;c4<DM/4;c4++){
        F4U wv; wv.f = w4[c4];
#pragma unroll
        for(int t=0;t<16;t++){
            F4U xv; xv.f = *reinterpret_cast<const float4*>(&xt[t*DM+c4*4]);
            acc[t]=fma2(wv.u[0],xv.u[0],acc[t]);
            acc[t]=fma2(wv.u[1],xv.u[1],acc[t]);
        }
    }
    if(j<DI){
#pragma unroll
        for(int t=0;t<16;t++) g_xcraw[(size_t)(tb+t)*DI+j]=LOF(acc[t])+HIF(acc[t]);
    } else {
        int jz=j-DI;
#pragma unroll
        for(int t=0;t<16;t++) g_z[(size_t)(tb+t)*DI+jz]=fsilu(LOF(acc[t])+HIF(acc[t]));
    }
}

/* ------------- depthwise 3x3 conv, 4 outputs/thread ------------- */
__global__ void k_conv(const float* __restrict__ cw, const float* __restrict__ cb)
{
    int l0 = blockIdx.x*4;
    int b  = blockIdx.y;
    int d  = threadIdx.x;
    int h  = l0/WW, w0 = l0%WW;
    float wt[9];
#pragma unroll
    for(int i=0;i<9;i++) wt[i]=cw[d*9+i];
    float bias=cb[d];
    const float* base = g_xcraw + (size_t)b*LL*DI + d;
    float s[4];
#pragma unroll
    for(int i=0;i<4;i++) s[i]=bias;
#pragma unroll
    for(int kh=0;kh<3;kh++){
        int h2=h+kh-1;
        if((unsigned)h2>=HH) continue;
#pragma unroll
        for(int c=0;c<6;c++){
            int w2=w0+c-1;
            if((unsigned)w2>=WW) continue;
            float v = base[(size_t)(h2*WW+w2)*DI];
#pragma unroll
            for(int i=0;i<4;i++){
                int kw=c-i;
                if(kw>=0 && kw<3) s[i]+=v*wt[kh*3+kw];
            }
        }
    }
#pragma unroll
    for(int i=0;i<4;i++)
        g_xch[((size_t)b*LL + l0+i)*DI + d] = fsilu(s[i]);
}

/* ------------- x_proj into permuted rows (B block, C block) ------------- */
__global__ void k_xproj(const float* __restrict__ xw)
{
    __shared__ float tok[16*DI];
    int tb = blockIdx.x*16;
    int b = tb/LL, l0 = tb%LL;
    for(int i=threadIdx.x;i<16*DI;i+=blockDim.x) tok[i]=g_xch[((size_t)b*LL+l0)*DI+i];
    __syncthreads();
    u64 acc[16];
    int kc=threadIdx.x;
    int k=kc/38, c=kc%38;
    bool active = kc < 114;
    if(active){
#pragma unroll
        for(int t=0;t<16;t++) acc[t]=0ull;
        const float4* w4 = reinterpret_cast<const float4*>(xw + (size_t)(k*38+c)*DI);
        for(int d4=0; d4<DI/4; d4++){
            F4U wv; wv.f=w4[d4];
#pragma unroll
            for(int t=0;t<16;t++){
                F4U xv; xv.f=*reinterpret_cast<const float4*>(&tok[t*DI+d4*4]);
                acc[t]=fma2(wv.u[0],xv.u[0],acc[t]);
                acc[t]=fma2(wv.u[1],xv.u[1],acc[t]);
            }
        }
    }
    __syncthreads();
    float* stage = tok;   /* 48 rows * 40 = 1920 <= 3072 */
    if(active){
        int slot = (c<RR)? c : (c<RR+NS ? 8+(c-RR) : 24+(c-RR-NS));
#pragma unroll
        for(int t=0;t<16;t++) stage[(k*16+t)*XD+slot]=LOF(acc[t])+HIF(acc[t]);
    }
    __syncthreads();
    for(int i=threadIdx.x;i<48*XD;i+=blockDim.x){
        int rr=i/XD, slot=i%XD;
        int k2=rr/16, t=rr%16;
        int lsp=l0+t;
        int p = (k2==0)? lsp : (k2==1 ? (lsp%WW)*HH + lsp/WW : LL-1-lsp);
        g_xdbl[(((size_t)b*KK+k2)*LL+p)*XD+slot]=stage[i];
    }
}

/* ------------- precompute {e1, dt*u} into [bk][l][d] ------------- */
__global__ void k_delta(const float* __restrict__ dtw_g, const float* __restrict__ dtb_g,
                        const float* __restrict__ alog)
{
    __shared__ float s_r[32][RR];
    int d  = threadIdx.x;
    int k  = blockIdx.y, b = blockIdx.z;
    int l0 = blockIdx.x * 32;
    float dtw[RR];
#pragma unroll
    for (int r=0;r<RR;r++) dtw[r] = dtw_g[(size_t)(k*DI+d)*RR + r];
    float bias = dtb_g[k*DI + d];
    float A0   = -__expf(alog[(size_t)(k*DI+d)*NS]);
    const float* xr = g_xdbl + ((size_t)(b*KK+k)*LL)*XD;
    {
        int t = threadIdx.x / RR, r = threadIdx.x % RR;   /* 192 = 32*6 */
        s_r[t][r] = xr[(size_t)(l0+t)*XD + r];
    }
    __syncthreads();
    float2* po = g_pre + ((size_t)(b*KK+k)*LL + l0)*DI + d;
#pragma unroll 4
    for (int t=0;t<32;t++){
        int p = l0 + t;
        int sp;
        if (k==0)      sp = p;
        else if (k==1) sp = (p % HH)*WW + p/HH;
        else           sp = LL-1-p;
        float u = g_xch[((size_t)b*LL + sp)*DI + d];
        float s = bias;
#pragma unroll
        for (int r=0;r<RR;r++) s += dtw[r]*s_r[t][r];
        float dt = fmaxf(s,0.f) + __logf(1.f + __expf(-fabsf(s)));
        float e1 = __expf(dt * A0);
        po[(size_t)t*DI] = make_float2(e1, dt*u);
    }
}

/* ------------- scan pass 1: segment summaries, h0=0 ------------- */
__global__ void k_scan1(const float* __restrict__ alog)
{
    __shared__ float sb[LSEG*32];
    int seg = blockIdx.x, bk = blockIdx.y;
    int d = threadIdx.x;
    int chain = bk*DI + d;
    int k = bk % KK;
    int l0 = seg*LSEG;
    for(int i=threadIdx.x;i<LSEG*32;i+=blockDim.x)
        sb[i] = g_xdbl[((size_t)bk*LL + l0 + (i>>5))*XD + 8 + (i&31)];
    __syncthreads();

    const float* ar = alog + (size_t)(k*DI+d)*NS;
    float a0 = ar[0];
    bool unit=true;
#pragma unroll
    for(int n=0;n<NS;n++){
        float r=__expf(ar[n]-a0);
        unit = unit && (fabsf(r-(float)(n+1))<1e-3f);
    }
    bool wunit = __all_sync(0xffffffffu, unit);
    const float2* pre = g_pre + (size_t)bk*LL*DI + d;
    float pe=1.f;
    if(wunit){
        u64 h2[8];
#pragma unroll
        for(int j=0;j<8;j++) h2[j]=0ull;
        for(int i=0;i<LSEG;i++){
            float2 ed = pre[(size_t)(l0+i)*DI];
            float e1=ed.x, e1sq=e1*e1;
            pe*=e1;
            u64 du2=F2P(ed.y,ed.y);
            u64 e2p=F2P(e1sq,e1sq);
            u64 a=F2P(e1,e1sq);
            const F4U* bp=reinterpret_cast<const F4U*>(&sb[i*32]);
#pragma unroll
            for(int j=0;j<4;j++){
                F4U bv=bp[j];
                h2[2*j]  = fma2(a,h2[2*j],  mul2(du2,bv.u[0])); a=mul2(a,e2p);
                h2[2*j+1]= fma2(a,h2[2*j+1],mul2(du2,bv.u[1])); a=mul2(a,e2p);
            }
        }
#pragma unroll
        for(int j=0;j<8;j++){
            g_segq[seg][2*j][chain]  =LOF(h2[j]);
            g_segq[seg][2*j+1][chain]=HIF(h2[j]);
        }
    } else {
        float rn[NS], h[NS];
#pragma unroll
        for(int n=0;n<NS;n++){ rn[n]=__expf(ar[n]-a0); h[n]=0.f; }
        for(int i=0;i<LSEG;i++){
            float2 ed=pre[(size_t)(l0+i)*DI];
            pe*=ed.x;
            float lg=__log2f(ed.x), du=ed.y;
#pragma unroll
            for(int n=0;n<NS;n++)
                h[n]=exp2f(lg*rn[n])*h[n] + du*sb[i*32+n];
        }
#pragma unroll
        for(int n=0;n<NS;n++) g_segq[seg][n][chain]=h[n];
    }
    g_segp[seg][chain]=pe;
}

/* ------------- combine: sequential over segments ------------- */
__global__ void k_comb(const float* __restrict__ alog)
{
    int t = blockIdx.x*blockDim.x + threadIdx.x;   /* CH*NS threads */
    int n = t / CH, chain = t % CH;
    int d = chain % DI, k = (chain / DI) % KK;
    const float* ar = alog + (size_t)(k*DI+d)*NS;
    float ratio = __expf(ar[n] - ar[0]);
    float h = 0.f;
    g_hin[0][n][chain] = 0.f;
#pragma unroll 4
    for (int s=1;s<SS;s++){
        float pe = g_segp[s-1][chain];
        float q  = g_segq[s-1][n][chain];
        h = exp2f(__log2f(pe)*ratio)*h + q;
        g_hin[s][n][chain] = h;
    }
}

/* ------------- scan pass 2: rescan with h_init, emit y ------------- */
__global__ void k_scan2(const float* __restrict__ alog)
{
    __shared__ float sb[LSEG*32];
    int seg=blockIdx.x, bk=blockIdx.y;
    int d=threadIdx.x;
    int chain=bk*DI+d;
    int k=bk%KK, b=bk/KK;
    int l0=seg*LSEG;
    for(int i=threadIdx.x;i<LSEG*32;i+=blockDim.x)
        sb[i]=g_xdbl[((size_t)bk*LL+l0+(i>>5))*XD+8+(i&31)];
    __syncthreads();
    const float* ar=alog+(size_t)(k*DI+d)*NS;
    float a0=ar[0];
    bool unit=true;
#pragma unroll
    for(int n=0;n<NS;n++){ float r=__expf(ar[n]-a0); unit=unit&&(fabsf(r-(float)(n+1))<1e-3f); }
    bool wunit=__all_sync(0xffffffffu,unit);
    const float2* pre=g_pre+(size_t)bk*LL*DI+d;
    float* yout=g_ys[k]+(size_t)b*LL*DI+d;
    int hh=l0%HH, wc=l0/HH;
    if(wunit){
        u64 h2[8];
#pragma unroll
        for(int j=0;j<8;j++) h2[j]=F2P(g_hin[seg][2*j][chain], g_hin[seg][2*j+1][chain]);
        for(int i=0;i<LSEG;i++){
            float2 ed=pre[(size_t)(l0+i)*DI];
            float e1=ed.x, e1sq=e1*e1;
            u64 du2=F2P(ed.y,ed.y), e2p=F2P(e1sq,e1sq), a=F2P(e1,e1sq);
            const F4U* bp=reinterpret_cast<const F4U*>(&sb[i*32]);
            const F4U* cp=reinterpret_cast<const F4U*>(&sb[i*32+16]);
            u64 y2=0ull;
#pragma unroll
            for(int j=0;j<4;j++){
                F4U bv=bp[j]; F4U cv=cp[j];
                h2[2*j]  =fma2(a,h2[2*j],  mul2(du2,bv.u[0])); y2=fma2(h2[2*j],  cv.u[0],y2); a=mul2(a,e2p);
                h2[2*j+1]=fma2(a,h2[2*j+1],mul2(du2,bv.u[1])); y2=fma2(h2[2*j+1],cv.u[1],y2); a=mul2(a,e2p);
            }
            float y=LOF(y2)+HIF(y2);
            int l=l0+i, pos;
            if(k==0) pos=l;
            else if(k==1){ pos=hh*WW+wc; hh++; if(hh==HH){hh=0;wc++;} }
            else pos=LL-1-l;
            yout[(size_t)pos*DI]=y;
        }
    } else {
        float rn[NS],h[NS];
#pragma unroll
        for(int n=0;n<NS;n++){ rn[n]=__expf(ar[n]-a0); h[n]=g_hin[seg][n][chain]; }
        for(int i=0;i<LSEG;i++){
            float2 ed=pre[(size_t)(l0+i)*DI];
            float lg=__log2f(ed.x), du=ed.y, y=0.f;
#pragma unroll
            for(int n=0;n<NS;n++){
                h[n]=exp2f(lg*rn[n])*h[n]+du*sb[i*32+n];
                y+=h[n]*sb[i*32+16+n];
            }
            int l=l0+i,pos;
            if(k==0)pos=l;
            else if(k==1){pos=hh*WW+wc;hh++;if(hh==HH){hh=0;wc++;}}
            else pos=LL-1-l;
            yout[(size_t)pos*DI]=y;
        }
    }
}

/* ------------- merge + D-term + gating + out_proj ------------- */
__global__ void k_out(const float* __restrict__ ow, const float* __restrict__ Ds,
                      float* __restrict__ out)
{
    __shared__ float yz[16*DI];
    int tb=blockIdx.x*16;
    size_t base=(size_t)tb*DI;
    for(int i=threadIdx.x;i<16*DI;i+=blockDim.x){
        int dd=i%DI;
        float dsum=Ds[dd]+Ds[DI+dd]+Ds[2*DI+dd];
        float v=g_ys[0][base+i]+g_ys[1][base+i]+g_ys[2][base+i]+dsum*g_xch[base+i];
        yz[i]=v*g_z[base+i];
    }
    __syncthreads();
    int j=threadIdx.x;
    if(j<DM){
        u64 acc[16];
#pragma unroll
        for(int t=0;t<16;t++) acc[t]=0ull;
        const float4* w4=reinterpret_cast<const float4*>(ow+(size_t)j*DI);
        for(int d4=0;d4<DI/4;d4++){
            F4U wv; wv.f=w4[d4];
#pragma unroll
            for(int t=0;t<16;t++){
                F4U xv; xv.f=*reinterpret_cast<const float4*>(&yz[t*DI+d4*4]);
                acc[t]=fma2(wv.u[0],xv.u[0],acc[t]);
                acc[t]=fma2(wv.u[1],xv.u[1],acc[t]);
            }
        }
#pragma unroll
        for(int t=0;t<16;t++) out[(size_t)(tb+t)*DM+j]=LOF(acc[t])+HIF(acc[t]);
    }
}

/* ---------------- launcher ---------------- */
extern "C" void kernel_launch(void* const* d_in, const int* in_sizes, int n_in,
                              void* d_out, int out_size)
{
    const float* x    = (const float*)d_in[0];
    const float* inw  = (const float*)d_in[2];
    const float* cw   = (const float*)d_in[3];
    const float* cb   = (const float*)d_in[4];
    const float* xw   = (const float*)d_in[5];
    const float* dtw  = (const float*)d_in[6];
    const float* dtb  = (const float*)d_in[7];
    const float* alog = (const float*)d_in[8];
    const float* Ds   = (const float*)d_in[9];
    const float* ow   = (const float*)d_in[10];
    float* out = (float*)d_out;

    k_inproj<<<BB*LL/16, 384>>>(x, inw);
    k_conv  <<<dim3(LL/4, BB), DI>>>(cw, cb);
    k_xproj <<<BB*LL/16, 128>>>(xw);
    k_delta <<<dim3(LL/32, KK, BB), DI>>>(dtw, dtb, alog);
    k_scan1 <<<dim3(SS, BB*KK), DI>>>(alog);
    k_comb  <<<CH*NS/256, 256>>>(alog);
    k_scan2 <<<dim3(SS, BB*KK), DI>>>(alog);
    k_out   <<<BB*LL/16, 128>>>(ow, Ds, out);
}